// round 13
// baseline (speedup 1.0000x reference)
#include <cuda_runtime.h>
#include <cstdint>

// Problem shapes (fixed)
#define B_ 256
#define R_ 64
#define F_ 2048
#define H_ 512
#define D_ 512
#define MROWS (B_*R_)      // 16384 rows of the big GEMM

// GEMM tiling
#define KT 32              // K tile
#define MT 128             // M tile (2 batches)
#define NT 128             // N tile (4 n-chunks cover DIM=512)
#define NKT (F_/KT)        // 64 K iterations
#define NSTAGE 3

// smem: per stage A [128][9] uint4 (18432B), B [32][34] uint4 (17408B)
// B row stride 136 words: 136 mod 32 = 8 -> bank = 8*tig+gid (perfect perm)
#define AS_STAGE_U4 (128*9)                 // 1152
#define BS_STAGE_U4 (32*34)                 // 1088
#define AS_BYTES (NSTAGE*AS_STAGE_U4*16)    // 55296
#define BS_BYTES (NSTAGE*BS_STAGE_U4*16)    // 52224
#define SMEM_BYTES (AS_BYTES + BS_BYTES)    // 107520  (x2 CTAs = 215KB < 228KB)

// Scratch (device globals: no allocations allowed)
__device__ float    g_p[B_ * D_];          // prev @ W2 + b2
__device__ float    g_score[4 * MROWS];    // partial scores, one slab per n-chunk
__device__ uint32_t g_WwB[F_ * D_];        // W_w pre-rounded to tf32 (rna), same layout

// ---------------------------------------------------------------------------
// helpers
// ---------------------------------------------------------------------------
__device__ __forceinline__ void cp16(uint32_t dst, const void* src) {
    asm volatile("cp.async.cg.shared.global [%0], [%1], 16;" :: "r"(dst), "l"(src));
}
__device__ __forceinline__ uint32_t smem_u32(const void* p) {
    uint32_t a;
    asm("{ .reg .u64 t; cvta.to.shared.u64 t, %1; cvt.u32.u64 %0, t; }"
        : "=r"(a) : "l"(p));
    return a;
}
__device__ __forceinline__ void cp_commit() { asm volatile("cp.async.commit_group;"); }
__device__ __forceinline__ void cp_wait1()  { asm volatile("cp.async.wait_group 1;"); }
__device__ __forceinline__ void cp_wait0()  { asm volatile("cp.async.wait_group 0;"); }

__device__ __forceinline__ void mma_tf32(float* d, const uint32_t* a,
                                         uint32_t b0, uint32_t b1) {
    asm volatile(
        "mma.sync.aligned.m16n8k8.row.col.f32.tf32.tf32.f32 "
        "{%0,%1,%2,%3}, {%4,%5,%6,%7}, {%8,%9}, {%0,%1,%2,%3};\n"
        : "+f"(d[0]), "+f"(d[1]), "+f"(d[2]), "+f"(d[3])
        : "r"(a[0]), "r"(a[1]), "r"(a[2]), "r"(a[3]), "r"(b0), "r"(b1));
}

// ---------------------------------------------------------------------------
// Kernel 0: pre-round W_w to tf32 (rna) bits, same [F, D] layout
// ---------------------------------------------------------------------------
__global__ void __launch_bounds__(256) cvt_ww_kernel(const float* __restrict__ Ww) {
    const int i = blockIdx.x * 256 + threadIdx.x;      // uint4 index
    const float4 v = ((const float4*)Ww)[i];
    uint4 t;
    asm("cvt.rna.tf32.f32 %0, %1;" : "=r"(t.x) : "f"(v.x));
    asm("cvt.rna.tf32.f32 %0, %1;" : "=r"(t.y) : "f"(v.y));
    asm("cvt.rna.tf32.f32 %0, %1;" : "=r"(t.z) : "f"(v.z));
    asm("cvt.rna.tf32.f32 %0, %1;" : "=r"(t.w) : "f"(v.w));
    ((uint4*)g_WwB)[i] = t;
}

// ---------------------------------------------------------------------------
// Kernel 1: p[b,d] = prev[b,:] @ W2[:,d] + W2b[d]
// grid (32 bg, 4 dq), block 128: 128 CTAs (one wave over ~128 SMs).
// Each CTA: 8 batches x 128 d.  h-loop unrolled x8, ps as float4 broadcasts.
// ---------------------------------------------------------------------------
__global__ void __launch_bounds__(128) prep_p_kernel(
        const float* __restrict__ prev,
        const float* __restrict__ W2w,
        const float* __restrict__ W2b) {
    __shared__ float4 ps4[8 * 128];   // 8 batches x 512 floats
    const int bg = blockIdx.x;
    const int dq = blockIdx.y;
    const int tid = threadIdx.x;

    const float4* pv = (const float4*)(prev + (size_t)bg * 8 * 512);
    for (int i = tid; i < 1024; i += 128) ps4[i] = pv[i];
    __syncthreads();

    const int d = dq * 128 + tid;
    const float bias = W2b[d];
    float acc[8];
    #pragma unroll
    for (int i = 0; i < 8; i++) acc[i] = bias;

    for (int h = 0; h < 512; h += 8) {
        float w[8];
        #pragma unroll
        for (int j = 0; j < 8; j++) w[j] = W2w[(h + j) * 512 + d];
        #pragma unroll
        for (int i = 0; i < 8; i++) {
            const float4 p0 = ps4[i * 128 + (h >> 2)];
            const float4 p1 = ps4[i * 128 + (h >> 2) + 1];
            acc[i] = fmaf(p0.x, w[0], acc[i]);
            acc[i] = fmaf(p0.y, w[1], acc[i]);
            acc[i] = fmaf(p0.z, w[2], acc[i]);
            acc[i] = fmaf(p0.w, w[3], acc[i]);
            acc[i] = fmaf(p1.x, w[4], acc[i]);
            acc[i] = fmaf(p1.y, w[5], acc[i]);
            acc[i] = fmaf(p1.z, w[6], acc[i]);
            acc[i] = fmaf(p1.w, w[7], acc[i]);
        }
    }
    #pragma unroll
    for (int i = 0; i < 8; i++) g_p[(bg * 8 + i) * 512 + d] = acc[i];
}

// ---------------------------------------------------------------------------
// ncu-steering no-ops (put prep_p in ncu capture slot 6)
// ---------------------------------------------------------------------------
__global__ void steer_kernel() {}
__global__ void steer_kernel2() {}

// ---------------------------------------------------------------------------
// Kernel 2: per CTA, C[128,128] = feat_rows @ W_w[:, n-chunk] (tf32 mma.sync),
// then partial_score[row] = sum_d W3[d]*tanh(C + W_b[d] + p[b,d])
// grid (4 n-chunks, 128 m-tiles), 256 threads, 2 CTAs/SM,
// single-barrier 3-stage cp.async pipeline (refill issued before mma)
// ---------------------------------------------------------------------------
__global__ void __launch_bounds__(256, 2) gemm_score_kernel(
        const float* __restrict__ features,
        const float* __restrict__ Wb,
        const float* __restrict__ W3) {
    extern __shared__ uint4 smem[];
    uint32_t* As32 = (uint32_t*)smem;                        // [3][128][36] words
    uint32_t* Bs32 = (uint32_t*)(smem + NSTAGE*AS_STAGE_U4); // [3][32][136] words
    const uint32_t sbase = smem_u32(smem);
    const uint32_t sA = sbase;
    const uint32_t sB = sbase + AS_BYTES;

    const int tid  = threadIdx.x;
    const int wid  = tid >> 5;
    const int lane = tid & 31;
    const int gid  = lane >> 2;       // group id (row within frag)
    const int tig  = lane & 3;        // thread-in-group (k/col within frag)
    const int wm   = wid & 3;         // warp m position (4 x 32 rows)
    const int wn   = wid >> 2;        // warp n position (2 x 64 cols)
    const int n0   = blockIdx.x * NT; // n-chunk (fast dim -> co-resident share A)
    const int m0   = blockIdx.y * MT;

    const float* gA = features + (size_t)m0 * F_;
    const uint4* Bw4 = (const uint4*)g_WwB;   // row stride 128 uint4

    float acc[2][8][4];
    #pragma unroll
    for (int i = 0; i < 2; i++)
        #pragma unroll
        for (int j = 0; j < 8; j++)
            #pragma unroll
            for (int k = 0; k < 4; k++) acc[i][j][k] = 0.f;

    // --- async tile load: A 128x32 floats, B 32x128 tf32-bits ---
    auto load_tile = [&](int kt, int buf) {
        const float* a = gA + kt * KT;
        const uint32_t dstA = sA + buf * (AS_STAGE_U4 * 16);
        #pragma unroll
        for (int t = 0; t < 4; t++) {
            const int i = tid + t * 256;          // 1024 chunks
            const int row = i >> 3, c = i & 7;
            cp16(dstA + (uint32_t)(row * 144 + c * 16),
                 a + (size_t)row * F_ + c * 4);
        }
        const uint4* b = Bw4 + (size_t)(kt * 32) * 128 + (n0 >> 2);
        const uint32_t dstB = sB + buf * (BS_STAGE_U4 * 16);
        #pragma unroll
        for (int t = 0; t < 4; t++) {
            const int i = tid + t * 256;          // 1024 chunks
            const int kk = i >> 5, nq = i & 31;
            cp16(dstB + (uint32_t)(kk * 544 + nq * 16),
                 b + (size_t)kk * 128 + nq);
        }
        cp_commit();
    };

    load_tile(0, 0);
    load_tile(1, 1);

    int buf = 0;
    for (int kt = 0; kt < NKT; kt++) {
        if (kt + 1 < NKT) cp_wait1(); else cp_wait0();
        __syncthreads();          // tile kt visible; buffer (kt+2)%3 fully consumed

        // refill issued BEFORE compute: overlaps with this iteration's mma.
        if (kt + 2 < NKT) load_tile(kt + 2, (buf + 2 >= NSTAGE) ? buf + 2 - NSTAGE : buf + 2);

        const uint32_t* Ab = As32 + buf * (AS_STAGE_U4 * 4);
        const uint32_t* Bb = Bs32 + buf * (BS_STAGE_U4 * 4);
        #pragma unroll
        for (int k8 = 0; k8 < 4; k8++) {
            uint32_t a[2][4];
            const int kc = k8 * 8 + tig;
            #pragma unroll
            for (int mf = 0; mf < 2; mf++) {
                const int r0 = wm * 32 + mf * 16 + gid;
                a[mf][0] = Ab[r0 * 36 + kc];
                a[mf][1] = Ab[(r0 + 8) * 36 + kc];
                a[mf][2] = Ab[r0 * 36 + kc + 4];
                a[mf][3] = Ab[(r0 + 8) * 36 + kc + 4];
            }
            const uint32_t* Bp = Bb + (size_t)(k8 * 8 + tig) * 136 + wn * 64 + gid;
            #pragma unroll
            for (int nf = 0; nf < 8; nf++) {
                const uint32_t b0 = Bp[nf * 8];
                const uint32_t b1 = Bp[nf * 8 + 4 * 136];
                mma_tf32(acc[0][nf], a[0], b0, b1);
                mma_tf32(acc[1][nf], a[1], b0, b1);
            }
        }

        buf = (buf == NSTAGE - 1) ? 0 : buf + 1;
    }

    // -------- epilogue: score partials --------
    float part[4] = {0.f, 0.f, 0.f, 0.f};
    {
        // each warp's 32 rows lie inside one batch (wm*32 block within 64-row batch)
        const int b = (m0 + wm * 32) >> 6;
        const float* pB  = g_p + b * 512 + n0 + wn * 64;
        const float* w3B = W3 + n0 + wn * 64;
        const float* wbB = Wb + n0 + wn * 64;
        #pragma unroll
        for (int nf = 0; nf < 8; nf++) {
            #pragma unroll
            for (int c = 0; c < 2; c++) {
                const int dl = nf * 8 + 2 * tig + c;
                const float add = wbB[dl] + pB[dl];
                const float w3  = w3B[dl];
                float t0, t1, t2, t3;
                asm("tanh.approx.f32 %0, %1;" : "=f"(t0) : "f"(acc[0][nf][c]     + add));
                asm("tanh.approx.f32 %0, %1;" : "=f"(t1) : "f"(acc[0][nf][2 + c] + add));
                asm("tanh.approx.f32 %0, %1;" : "=f"(t2) : "f"(acc[1][nf][c]     + add));
                asm("tanh.approx.f32 %0, %1;" : "=f"(t3) : "f"(acc[1][nf][2 + c] + add));
                part[0] = fmaf(w3, t0, part[0]);   // row gid
                part[1] = fmaf(w3, t1, part[1]);   // row gid+8
                part[2] = fmaf(w3, t2, part[2]);   // row gid+16
                part[3] = fmaf(w3, t3, part[3]);   // row gid+24
            }
        }
    }
    // reduce over tig (lanes differing in bits 0..1 hold different d's)
    #pragma unroll
    for (int msk = 1; msk < 4; msk <<= 1) {
        #pragma unroll
        for (int i = 0; i < 4; i++)
            part[i] += __shfl_xor_sync(0xffffffffu, part[i], msk);
    }

    __syncthreads();                 // done with tile smem; repurpose
    float* scoreS = (float*)smem;    // [2][128]
    if (tig == 0) {
        const int rb = wm * 32 + gid;
        scoreS[wn * 128 + rb]      = part[0];
        scoreS[wn * 128 + rb + 8]  = part[1];
        scoreS[wn * 128 + rb + 16] = part[2];
        scoreS[wn * 128 + rb + 24] = part[3];
    }
    __syncthreads();
    if (tid < 128) {
        g_score[blockIdx.x * MROWS + m0 + tid] = scoreS[tid] + scoreS[128 + tid];
    }
}

// ---------------------------------------------------------------------------
// Kernel 3: softmax over 64 scores + weighted feature sum.
// grid (4 column-quarters, 256 batches), 128 threads; r-loop unroll 16.
// ---------------------------------------------------------------------------
__global__ void __launch_bounds__(128) softmax_q_kernel(
        const float* __restrict__ features,
        float* __restrict__ out) {
    __shared__ float s_s[64];
    __shared__ float aw_s[64];
    const int quarter = blockIdx.x;  // 0..3 (128 float4 columns each)
    const int b       = blockIdx.y;
    const int tid     = threadIdx.x;

    if (tid < 64) {
        float v = 0.f;
        #pragma unroll
        for (int p = 0; p < 4; p++) v += g_score[p * MROWS + b * 64 + tid];
        s_s[tid] = v;
    }
    __syncthreads();

    // every thread computes identical max/sum (deterministic, smem broadcast)
    float m = -1e30f;
    #pragma unroll 8
    for (int i = 0; i < 64; i++) m = fmaxf(m, s_s[i]);
    float sum = 0.f;
    #pragma unroll 8
    for (int i = 0; i < 64; i++) sum += expf(s_s[i] - m);

    if (tid < 64) aw_s[tid] = expf(s_s[tid] - m) / sum;
    __syncthreads();

    const int col = quarter * 128 + tid;       // float4 column index (0..511)
    const float4* f4 = (const float4*)(features + (size_t)b * R_ * F_) + col;
    float4 a0 = {0.f, 0.f, 0.f, 0.f};
    #pragma unroll
    for (int r = 0; r < 64; r += 16) {
        float4 x[16];
        float  w[16];
        #pragma unroll
        for (int j = 0; j < 16; j++) { x[j] = f4[(size_t)(r + j) * 512]; w[j] = aw_s[r + j]; }
        #pragma unroll
        for (int j = 0; j < 16; j++) {
            a0.x = fmaf(w[j], x[j].x, a0.x); a0.y = fmaf(w[j], x[j].y, a0.y);
            a0.z = fmaf(w[j], x[j].z, a0.z); a0.w = fmaf(w[j], x[j].w, a0.w);
        }
    }
    ((float4*)out)[(size_t)b * 512 + col] = a0;
}

// ---------------------------------------------------------------------------
// kernel_launch
// inputs: 0 features, 1 prev, 2 W_w, 3 W_b, 4 W2_w, 5 W2_b, 6 W3_w, 7 W3_b
// (W3_b unused: softmax is shift-invariant)
// order: cvt(3) steer(4) steer2(5) prep(6) gemm(7) softmax(8)
//  -> ncu slot 6 profiles prep_p this round
// ---------------------------------------------------------------------------
extern "C" void kernel_launch(void* const* d_in, const int* in_sizes, int n_in,
                              void* d_out, int out_size) {
    const float* features = (const float*)d_in[0];
    const float* prev     = (const float*)d_in[1];
    const float* Ww       = (const float*)d_in[2];
    const float* Wb       = (const float*)d_in[3];
    const float* W2w      = (const float*)d_in[4];
    const float* W2b      = (const float*)d_in[5];
    const float* W3w      = (const float*)d_in[6];
    float* out = (float*)d_out;

    cudaFuncSetAttribute(gemm_score_kernel,
                         cudaFuncAttributeMaxDynamicSharedMemorySize, SMEM_BYTES);

    cvt_ww_kernel<<<(F_ * D_ / 4) / 256, 256>>>(Ww);
    steer_kernel<<<1, 1>>>();
    steer_kernel2<<<1, 1>>>();
    prep_p_kernel<<<dim3(32, 4), 128>>>(prev, W2w, W2b);
    gemm_score_kernel<<<dim3(4, 128), 256, SMEM_BYTES>>>(features, Wb, W3w);
    softmax_q_kernel<<<dim3(4, B_), 128>>>(features, out);
}

// round 14
// speedup vs baseline: 1.1713x; 1.1713x over previous
#include <cuda_runtime.h>
#include <cstdint>

// Problem shapes (fixed)
#define B_ 256
#define R_ 64
#define F_ 2048
#define H_ 512
#define D_ 512
#define MROWS (B_*R_)      // 16384 rows of the big GEMM

// GEMM tiling
#define KT 32              // K tile
#define MT 128             // M tile (2 batches)
#define NT 128             // N tile (4 n-chunks cover DIM=512)
#define NKT (F_/KT)        // 64 K iterations
#define NSTAGE 3

// smem: per stage A [128][9] uint4 (18432B), B [32][34] uint4 (17408B)
// B row stride 136 words: 136 mod 32 = 8 -> bank = 8*tig+gid (perfect perm)
#define AS_STAGE_U4 (128*9)                 // 1152
#define BS_STAGE_U4 (32*34)                 // 1088
#define AS_BYTES (NSTAGE*AS_STAGE_U4*16)    // 55296
#define BS_BYTES (NSTAGE*BS_STAGE_U4*16)    // 52224
#define SMEM_BYTES (AS_BYTES + BS_BYTES)    // 107520  (x2 CTAs = 215KB < 228KB)

// Scratch (device globals: no allocations allowed)
__device__ float    g_p0[B_ * D_];         // prev @ W2 (h 0..255) + W2b
__device__ float    g_p1[B_ * D_];         // prev @ W2 (h 256..511)
__device__ float    g_score[4 * MROWS];    // partial scores, one slab per n-chunk
__device__ uint32_t g_WwB[F_ * D_];        // W_w pre-rounded to tf32 (rna), same layout

// ---------------------------------------------------------------------------
// helpers
// ---------------------------------------------------------------------------
__device__ __forceinline__ void cp16(uint32_t dst, const void* src) {
    asm volatile("cp.async.cg.shared.global [%0], [%1], 16;" :: "r"(dst), "l"(src));
}
__device__ __forceinline__ uint32_t smem_u32(const void* p) {
    uint32_t a;
    asm("{ .reg .u64 t; cvta.to.shared.u64 t, %1; cvt.u32.u64 %0, t; }"
        : "=r"(a) : "l"(p));
    return a;
}
__device__ __forceinline__ void cp_commit() { asm volatile("cp.async.commit_group;"); }
__device__ __forceinline__ void cp_wait1()  { asm volatile("cp.async.wait_group 1;"); }
__device__ __forceinline__ void cp_wait0()  { asm volatile("cp.async.wait_group 0;"); }

__device__ __forceinline__ void mma_tf32(float* d, const uint32_t* a,
                                         uint32_t b0, uint32_t b1) {
    asm volatile(
        "mma.sync.aligned.m16n8k8.row.col.f32.tf32.tf32.f32 "
        "{%0,%1,%2,%3}, {%4,%5,%6,%7}, {%8,%9}, {%0,%1,%2,%3};\n"
        : "+f"(d[0]), "+f"(d[1]), "+f"(d[2]), "+f"(d[3])
        : "r"(a[0]), "r"(a[1]), "r"(a[2]), "r"(a[3]), "r"(b0), "r"(b1));
}

// ---------------------------------------------------------------------------
// Kernel 0: pre-round W_w to tf32 (rna) bits, same [F, D] layout
// ---------------------------------------------------------------------------
__global__ void __launch_bounds__(256) cvt_ww_kernel(const float* __restrict__ Ww) {
    const int i = blockIdx.x * 256 + threadIdx.x;      // uint4 index
    const float4 v = ((const float4*)Ww)[i];
    uint4 t;
    asm("cvt.rna.tf32.f32 %0, %1;" : "=r"(t.x) : "f"(v.x));
    asm("cvt.rna.tf32.f32 %0, %1;" : "=r"(t.y) : "f"(v.y));
    asm("cvt.rna.tf32.f32 %0, %1;" : "=r"(t.z) : "f"(v.z));
    asm("cvt.rna.tf32.f32 %0, %1;" : "=r"(t.w) : "f"(v.w));
    ((uint4*)g_WwB)[i] = t;
}

// ---------------------------------------------------------------------------
// Kernel 1: partial p over an h-half:
//   g_p{hs}[b,d] = sum_{h in half} prev[b,h]*W2w[h,d]  (+ W2b[d] if hs==0)
// grid (64 bg x 8), block 128: bg covers 4 batches; y = dq(4) + 4*hs(2).
// 512 CTAs -> ~3.5 CTAs/SM, ~14 warps/SM; per-thread chain 1024 FMA.
// ---------------------------------------------------------------------------
__global__ void __launch_bounds__(128) prep_p_kernel(
        const float* __restrict__ prev,
        const float* __restrict__ W2w,
        const float* __restrict__ W2b) {
    __shared__ float4 ps4[4 * 64];    // 4 batches x 256 floats (this h-half)
    const int bg  = blockIdx.x;       // 4 batches each
    const int dq  = blockIdx.y & 3;   // 128-d quarter
    const int hs  = blockIdx.y >> 2;  // h-half
    const int tid = threadIdx.x;
    const int h0  = hs * 256;

    for (int i = tid; i < 256; i += 128) {
        const int bb = i >> 6, hc = i & 63;
        ps4[i] = ((const float4*)(prev + (size_t)(bg * 4 + bb) * 512 + h0))[hc];
    }
    __syncthreads();

    const int d = dq * 128 + tid;
    float acc[4];
    const float init = (hs == 0) ? W2b[d] : 0.f;
    #pragma unroll
    for (int i = 0; i < 4; i++) acc[i] = init;

    for (int h = 0; h < 256; h += 8) {
        float w[8];
        #pragma unroll
        for (int j = 0; j < 8; j++) w[j] = W2w[(h0 + h + j) * 512 + d];
        #pragma unroll
        for (int i = 0; i < 4; i++) {
            const float4 p0 = ps4[i * 64 + (h >> 2)];
            const float4 p1 = ps4[i * 64 + (h >> 2) + 1];
            acc[i] = fmaf(p0.x, w[0], acc[i]);
            acc[i] = fmaf(p0.y, w[1], acc[i]);
            acc[i] = fmaf(p0.z, w[2], acc[i]);
            acc[i] = fmaf(p0.w, w[3], acc[i]);
            acc[i] = fmaf(p1.x, w[4], acc[i]);
            acc[i] = fmaf(p1.y, w[5], acc[i]);
            acc[i] = fmaf(p1.z, w[6], acc[i]);
            acc[i] = fmaf(p1.w, w[7], acc[i]);
        }
    }
    float* gp = hs ? g_p1 : g_p0;
    #pragma unroll
    for (int i = 0; i < 4; i++) gp[(size_t)(bg * 4 + i) * 512 + d] = acc[i];
}

// ---------------------------------------------------------------------------
// ncu-steering no-ops (put prep_p in ncu capture slot 6)
// ---------------------------------------------------------------------------
__global__ void steer_kernel() {}
__global__ void steer_kernel2() {}

// ---------------------------------------------------------------------------
// Kernel 2: per CTA, C[128,128] = feat_rows @ W_w[:, n-chunk] (tf32 mma.sync),
// then partial_score[row] = sum_d W3[d]*tanh(C + W_b[d] + p0[b,d] + p1[b,d])
// grid (4 n-chunks, 128 m-tiles), 256 threads, 2 CTAs/SM,
// single-barrier 3-stage cp.async pipeline (refill issued before mma)
// ---------------------------------------------------------------------------
__global__ void __launch_bounds__(256, 2) gemm_score_kernel(
        const float* __restrict__ features,
        const float* __restrict__ Wb,
        const float* __restrict__ W3) {
    extern __shared__ uint4 smem[];
    uint32_t* As32 = (uint32_t*)smem;                        // [3][128][36] words
    uint32_t* Bs32 = (uint32_t*)(smem + NSTAGE*AS_STAGE_U4); // [3][32][136] words
    const uint32_t sbase = smem_u32(smem);
    const uint32_t sA = sbase;
    const uint32_t sB = sbase + AS_BYTES;

    const int tid  = threadIdx.x;
    const int wid  = tid >> 5;
    const int lane = tid & 31;
    const int gid  = lane >> 2;       // group id (row within frag)
    const int tig  = lane & 3;        // thread-in-group (k/col within frag)
    const int wm   = wid & 3;         // warp m position (4 x 32 rows)
    const int wn   = wid >> 2;        // warp n position (2 x 64 cols)
    const int n0   = blockIdx.x * NT; // n-chunk (fast dim -> co-resident share A)
    const int m0   = blockIdx.y * MT;

    const float* gA = features + (size_t)m0 * F_;
    const uint4* Bw4 = (const uint4*)g_WwB;   // row stride 128 uint4

    float acc[2][8][4];
    #pragma unroll
    for (int i = 0; i < 2; i++)
        #pragma unroll
        for (int j = 0; j < 8; j++)
            #pragma unroll
            for (int k = 0; k < 4; k++) acc[i][j][k] = 0.f;

    // --- async tile load: A 128x32 floats, B 32x128 tf32-bits ---
    auto load_tile = [&](int kt, int buf) {
        const float* a = gA + kt * KT;
        const uint32_t dstA = sA + buf * (AS_STAGE_U4 * 16);
        #pragma unroll
        for (int t = 0; t < 4; t++) {
            const int i = tid + t * 256;          // 1024 chunks
            const int row = i >> 3, c = i & 7;
            cp16(dstA + (uint32_t)(row * 144 + c * 16),
                 a + (size_t)row * F_ + c * 4);
        }
        const uint4* b = Bw4 + (size_t)(kt * 32) * 128 + (n0 >> 2);
        const uint32_t dstB = sB + buf * (BS_STAGE_U4 * 16);
        #pragma unroll
        for (int t = 0; t < 4; t++) {
            const int i = tid + t * 256;          // 1024 chunks
            const int kk = i >> 5, nq = i & 31;
            cp16(dstB + (uint32_t)(kk * 544 + nq * 16),
                 b + (size_t)kk * 128 + nq);
        }
        cp_commit();
    };

    load_tile(0, 0);
    load_tile(1, 1);

    int buf = 0;
    for (int kt = 0; kt < NKT; kt++) {
        if (kt + 1 < NKT) cp_wait1(); else cp_wait0();
        __syncthreads();          // tile kt visible; buffer (kt+2)%3 fully consumed

        // refill issued BEFORE compute: overlaps with this iteration's mma.
        if (kt + 2 < NKT) load_tile(kt + 2, (buf + 2 >= NSTAGE) ? buf + 2 - NSTAGE : buf + 2);

        const uint32_t* Ab = As32 + buf * (AS_STAGE_U4 * 4);
        const uint32_t* Bb = Bs32 + buf * (BS_STAGE_U4 * 4);
        #pragma unroll
        for (int k8 = 0; k8 < 4; k8++) {
            uint32_t a[2][4];
            const int kc = k8 * 8 + tig;
            #pragma unroll
            for (int mf = 0; mf < 2; mf++) {
                const int r0 = wm * 32 + mf * 16 + gid;
                a[mf][0] = Ab[r0 * 36 + kc];
                a[mf][1] = Ab[(r0 + 8) * 36 + kc];
                a[mf][2] = Ab[r0 * 36 + kc + 4];
                a[mf][3] = Ab[(r0 + 8) * 36 + kc + 4];
            }
            const uint32_t* Bp = Bb + (size_t)(k8 * 8 + tig) * 136 + wn * 64 + gid;
            #pragma unroll
            for (int nf = 0; nf < 8; nf++) {
                const uint32_t b0 = Bp[nf * 8];
                const uint32_t b1 = Bp[nf * 8 + 4 * 136];
                mma_tf32(acc[0][nf], a[0], b0, b1);
                mma_tf32(acc[1][nf], a[1], b0, b1);
            }
        }

        buf = (buf == NSTAGE - 1) ? 0 : buf + 1;
    }

    // -------- epilogue: score partials --------
    float part[4] = {0.f, 0.f, 0.f, 0.f};
    {
        // each warp's 32 rows lie inside one batch (wm*32 block within 64-row batch)
        const int b = (m0 + wm * 32) >> 6;
        const float* p0B = g_p0 + b * 512 + n0 + wn * 64;
        const float* p1B = g_p1 + b * 512 + n0 + wn * 64;
        const float* w3B = W3 + n0 + wn * 64;
        const float* wbB = Wb + n0 + wn * 64;
        #pragma unroll
        for (int nf = 0; nf < 8; nf++) {
            #pragma unroll
            for (int c = 0; c < 2; c++) {
                const int dl = nf * 8 + 2 * tig + c;
                const float add = wbB[dl] + p0B[dl] + p1B[dl];
                const float w3  = w3B[dl];
                float t0, t1, t2, t3;
                asm("tanh.approx.f32 %0, %1;" : "=f"(t0) : "f"(acc[0][nf][c]     + add));
                asm("tanh.approx.f32 %0, %1;" : "=f"(t1) : "f"(acc[0][nf][2 + c] + add));
                asm("tanh.approx.f32 %0, %1;" : "=f"(t2) : "f"(acc[1][nf][c]     + add));
                asm("tanh.approx.f32 %0, %1;" : "=f"(t3) : "f"(acc[1][nf][2 + c] + add));
                part[0] = fmaf(w3, t0, part[0]);   // row gid
                part[1] = fmaf(w3, t1, part[1]);   // row gid+8
                part[2] = fmaf(w3, t2, part[2]);   // row gid+16
                part[3] = fmaf(w3, t3, part[3]);   // row gid+24
            }
        }
    }
    // reduce over tig (lanes differing in bits 0..1 hold different d's)
    #pragma unroll
    for (int msk = 1; msk < 4; msk <<= 1) {
        #pragma unroll
        for (int i = 0; i < 4; i++)
            part[i] += __shfl_xor_sync(0xffffffffu, part[i], msk);
    }

    __syncthreads();                 // done with tile smem; repurpose
    float* scoreS = (float*)smem;    // [2][128]
    if (tig == 0) {
        const int rb = wm * 32 + gid;
        scoreS[wn * 128 + rb]      = part[0];
        scoreS[wn * 128 + rb + 8]  = part[1];
        scoreS[wn * 128 + rb + 16] = part[2];
        scoreS[wn * 128 + rb + 24] = part[3];
    }
    __syncthreads();
    if (tid < 128) {
        g_score[blockIdx.x * MROWS + m0 + tid] = scoreS[tid] + scoreS[128 + tid];
    }
}

// ---------------------------------------------------------------------------
// Kernel 3: softmax over 64 scores + weighted feature sum.
// grid (4 column-quarters, 256 batches), 128 threads; r-loop unroll 16.
// ---------------------------------------------------------------------------
__global__ void __launch_bounds__(128) softmax_q_kernel(
        const float* __restrict__ features,
        float* __restrict__ out) {
    __shared__ float s_s[64];
    __shared__ float aw_s[64];
    const int quarter = blockIdx.x;  // 0..3 (128 float4 columns each)
    const int b       = blockIdx.y;
    const int tid     = threadIdx.x;

    if (tid < 64) {
        float v = 0.f;
        #pragma unroll
        for (int p = 0; p < 4; p++) v += g_score[p * MROWS + b * 64 + tid];
        s_s[tid] = v;
    }
    __syncthreads();

    // every thread computes identical max/sum (deterministic, smem broadcast)
    float m = -1e30f;
    #pragma unroll 8
    for (int i = 0; i < 64; i++) m = fmaxf(m, s_s[i]);
    float sum = 0.f;
    #pragma unroll 8
    for (int i = 0; i < 64; i++) sum += expf(s_s[i] - m);

    if (tid < 64) aw_s[tid] = expf(s_s[tid] - m) / sum;
    __syncthreads();

    const int col = quarter * 128 + tid;       // float4 column index (0..511)
    const float4* f4 = (const float4*)(features + (size_t)b * R_ * F_) + col;
    float4 a0 = {0.f, 0.f, 0.f, 0.f};
    #pragma unroll
    for (int r = 0; r < 64; r += 16) {
        float4 x[16];
        float  w[16];
        #pragma unroll
        for (int j = 0; j < 16; j++) { x[j] = f4[(size_t)(r + j) * 512]; w[j] = aw_s[r + j]; }
        #pragma unroll
        for (int j = 0; j < 16; j++) {
            a0.x = fmaf(w[j], x[j].x, a0.x); a0.y = fmaf(w[j], x[j].y, a0.y);
            a0.z = fmaf(w[j], x[j].z, a0.z); a0.w = fmaf(w[j], x[j].w, a0.w);
        }
    }
    ((float4*)out)[(size_t)b * 512 + col] = a0;
}

// ---------------------------------------------------------------------------
// kernel_launch
// inputs: 0 features, 1 prev, 2 W_w, 3 W_b, 4 W2_w, 5 W2_b, 6 W3_w, 7 W3_b
// (W3_b unused: softmax is shift-invariant)
// order: cvt(3) steer(4) steer2(5) prep(6) gemm(7) softmax(8)
//  -> ncu slot 6 profiles prep_p (verifying the h-split fix)
// ---------------------------------------------------------------------------
extern "C" void kernel_launch(void* const* d_in, const int* in_sizes, int n_in,
                              void* d_out, int out_size) {
    const float* features = (const float*)d_in[0];
    const float* prev     = (const float*)d_in[1];
    const float* Ww       = (const float*)d_in[2];
    const float* Wb       = (const float*)d_in[3];
    const float* W2w      = (const float*)d_in[4];
    const float* W2b      = (const float*)d_in[5];
    const float* W3w      = (const float*)d_in[6];
    float* out = (float*)d_out;

    cudaFuncSetAttribute(gemm_score_kernel,
                         cudaFuncAttributeMaxDynamicSharedMemorySize, SMEM_BYTES);

    cvt_ww_kernel<<<(F_ * D_ / 4) / 256, 256>>>(Ww);
    steer_kernel<<<1, 1>>>();
    steer_kernel2<<<1, 1>>>();
    prep_p_kernel<<<dim3(64, 8), 128>>>(prev, W2w, W2b);
    gemm_score_kernel<<<dim3(4, 128), 256, SMEM_BYTES>>>(features, Wb, W3w);
    softmax_q_kernel<<<dim3(4, B_), 128>>>(features, out);
}

// round 15
// speedup vs baseline: 1.2207x; 1.0422x over previous
#include <cuda_runtime.h>
#include <cstdint>

// Problem shapes (fixed)
#define B_ 256
#define R_ 64
#define F_ 2048
#define H_ 512
#define D_ 512
#define MROWS (B_*R_)      // 16384 rows of the big GEMM

// GEMM tiling
#define KT 32              // K tile
#define MT 128             // M tile (2 batches)
#define NT 128             // N tile (4 n-chunks cover DIM=512)
#define NKT (F_/KT)        // 64 K iterations
#define NSTAGE 3

// smem: per stage A [128][9] uint4 (18432B), B [32][34] uint4 (17408B)
// B row stride 136 words: 136 mod 32 = 8 -> bank = 8*tig+gid (perfect perm)
#define AS_STAGE_U4 (128*9)                 // 1152
#define BS_STAGE_U4 (32*34)                 // 1088
#define AS_BYTES (NSTAGE*AS_STAGE_U4*16)    // 55296
#define BS_BYTES (NSTAGE*BS_STAGE_U4*16)    // 52224
#define SMEM_BYTES (AS_BYTES + BS_BYTES)    // 107520  (x2 CTAs = 215KB < 228KB)

// Scratch (device globals: no allocations allowed)
__device__ float    g_pp[4][B_ * D_];      // prev @ W2 partials per h-quarter
__device__ float    g_score[4 * MROWS];    // partial scores, one slab per n-chunk
__device__ uint32_t g_WwB[F_ * D_];        // W_w pre-rounded to tf32 (rna), same layout

// ---------------------------------------------------------------------------
// helpers
// ---------------------------------------------------------------------------
__device__ __forceinline__ void cp16(uint32_t dst, const void* src) {
    asm volatile("cp.async.cg.shared.global [%0], [%1], 16;" :: "r"(dst), "l"(src));
}
__device__ __forceinline__ uint32_t smem_u32(const void* p) {
    uint32_t a;
    asm("{ .reg .u64 t; cvta.to.shared.u64 t, %1; cvt.u32.u64 %0, t; }"
        : "=r"(a) : "l"(p));
    return a;
}
__device__ __forceinline__ void cp_commit() { asm volatile("cp.async.commit_group;"); }
__device__ __forceinline__ void cp_wait1()  { asm volatile("cp.async.wait_group 1;"); }
__device__ __forceinline__ void cp_wait0()  { asm volatile("cp.async.wait_group 0;"); }

__device__ __forceinline__ void mma_tf32(float* d, const uint32_t* a,
                                         uint32_t b0, uint32_t b1) {
    asm volatile(
        "mma.sync.aligned.m16n8k8.row.col.f32.tf32.tf32.f32 "
        "{%0,%1,%2,%3}, {%4,%5,%6,%7}, {%8,%9}, {%0,%1,%2,%3};\n"
        : "+f"(d[0]), "+f"(d[1]), "+f"(d[2]), "+f"(d[3])
        : "r"(a[0]), "r"(a[1]), "r"(a[2]), "r"(a[3]), "r"(b0), "r"(b1));
}

// ---------------------------------------------------------------------------
// Kernel 0: pre-round W_w to tf32 (rna) bits, same [F, D] layout
// ---------------------------------------------------------------------------
__global__ void __launch_bounds__(256) cvt_ww_kernel(const float* __restrict__ Ww) {
    const int i = blockIdx.x * 256 + threadIdx.x;      // uint4 index
    const float4 v = ((const float4*)Ww)[i];
    uint4 t;
    asm("cvt.rna.tf32.f32 %0, %1;" : "=r"(t.x) : "f"(v.x));
    asm("cvt.rna.tf32.f32 %0, %1;" : "=r"(t.y) : "f"(v.y));
    asm("cvt.rna.tf32.f32 %0, %1;" : "=r"(t.z) : "f"(v.z));
    asm("cvt.rna.tf32.f32 %0, %1;" : "=r"(t.w) : "f"(v.w));
    ((uint4*)g_WwB)[i] = t;
}

// ---------------------------------------------------------------------------
// Kernel 1: partial p over an h-quarter:
//   g_pp[hq][b,d] = sum_{h in quarter} prev[b,h]*W2w[h,d]  (+ W2b[d] if hq==0)
// grid (64 bg x 16), block 128: bg covers 4 batches; y = dq(4) + 4*hq(4).
// 2048 CTAs (~55 warps/SM over waves); per-thread chain 512 FMA / 64 loads.
// ---------------------------------------------------------------------------
__global__ void __launch_bounds__(128) prep_p_kernel(
        const float* __restrict__ prev,
        const float* __restrict__ W2w,
        const float* __restrict__ W2b) {
    __shared__ float4 ps4[4 * 32];    // 4 batches x 128 floats (this h-quarter)
    const int bg  = blockIdx.x;       // 4 batches each
    const int dq  = blockIdx.y & 3;   // 128-d quarter
    const int hq  = blockIdx.y >> 2;  // h-quarter (0..3)
    const int tid = threadIdx.x;
    const int h0  = hq * 128;

    if (tid < 128) {
        const int bb = tid >> 5, hc = tid & 31;
        ps4[tid] = ((const float4*)(prev + (size_t)(bg * 4 + bb) * 512 + h0))[hc];
    }
    __syncthreads();

    const int d = dq * 128 + tid;
    float acc[4];
    const float init = (hq == 0) ? W2b[d] : 0.f;
    #pragma unroll
    for (int i = 0; i < 4; i++) acc[i] = init;

    for (int h = 0; h < 128; h += 8) {
        float w[8];
        #pragma unroll
        for (int j = 0; j < 8; j++) w[j] = W2w[(h0 + h + j) * 512 + d];
        #pragma unroll
        for (int i = 0; i < 4; i++) {
            const float4 p0 = ps4[i * 32 + (h >> 2)];
            const float4 p1 = ps4[i * 32 + (h >> 2) + 1];
            acc[i] = fmaf(p0.x, w[0], acc[i]);
            acc[i] = fmaf(p0.y, w[1], acc[i]);
            acc[i] = fmaf(p0.z, w[2], acc[i]);
            acc[i] = fmaf(p0.w, w[3], acc[i]);
            acc[i] = fmaf(p1.x, w[4], acc[i]);
            acc[i] = fmaf(p1.y, w[5], acc[i]);
            acc[i] = fmaf(p1.z, w[6], acc[i]);
            acc[i] = fmaf(p1.w, w[7], acc[i]);
        }
    }
    float* gp = g_pp[hq];
    #pragma unroll
    for (int i = 0; i < 4; i++) gp[(size_t)(bg * 4 + i) * 512 + d] = acc[i];
}

// ---------------------------------------------------------------------------
// ncu-steering no-ops (put prep_p in ncu capture slot 6)
// ---------------------------------------------------------------------------
__global__ void steer_kernel() {}
__global__ void steer_kernel2() {}

// ---------------------------------------------------------------------------
// Kernel 2: per CTA, C[128,128] = feat_rows @ W_w[:, n-chunk] (tf32 mma.sync),
// then partial_score[row] = sum_d W3[d]*tanh(C + W_b[d] + sum_hq pp[hq][b,d])
// grid (4 n-chunks, 128 m-tiles), 256 threads, 2 CTAs/SM,
// single-barrier 3-stage cp.async pipeline (refill issued before mma)
// ---------------------------------------------------------------------------
__global__ void __launch_bounds__(256, 2) gemm_score_kernel(
        const float* __restrict__ features,
        const float* __restrict__ Wb,
        const float* __restrict__ W3) {
    extern __shared__ uint4 smem[];
    uint32_t* As32 = (uint32_t*)smem;                        // [3][128][36] words
    uint32_t* Bs32 = (uint32_t*)(smem + NSTAGE*AS_STAGE_U4); // [3][32][136] words
    const uint32_t sbase = smem_u32(smem);
    const uint32_t sA = sbase;
    const uint32_t sB = sbase + AS_BYTES;

    const int tid  = threadIdx.x;
    const int wid  = tid >> 5;
    const int lane = tid & 31;
    const int gid  = lane >> 2;       // group id (row within frag)
    const int tig  = lane & 3;        // thread-in-group (k/col within frag)
    const int wm   = wid & 3;         // warp m position (4 x 32 rows)
    const int wn   = wid >> 2;        // warp n position (2 x 64 cols)
    const int n0   = blockIdx.x * NT; // n-chunk (fast dim -> co-resident share A)
    const int m0   = blockIdx.y * MT;

    const float* gA = features + (size_t)m0 * F_;
    const uint4* Bw4 = (const uint4*)g_WwB;   // row stride 128 uint4

    float acc[2][8][4];
    #pragma unroll
    for (int i = 0; i < 2; i++)
        #pragma unroll
        for (int j = 0; j < 8; j++)
            #pragma unroll
            for (int k = 0; k < 4; k++) acc[i][j][k] = 0.f;

    // --- async tile load: A 128x32 floats, B 32x128 tf32-bits ---
    auto load_tile = [&](int kt, int buf) {
        const float* a = gA + kt * KT;
        const uint32_t dstA = sA + buf * (AS_STAGE_U4 * 16);
        #pragma unroll
        for (int t = 0; t < 4; t++) {
            const int i = tid + t * 256;          // 1024 chunks
            const int row = i >> 3, c = i & 7;
            cp16(dstA + (uint32_t)(row * 144 + c * 16),
                 a + (size_t)row * F_ + c * 4);
        }
        const uint4* b = Bw4 + (size_t)(kt * 32) * 128 + (n0 >> 2);
        const uint32_t dstB = sB + buf * (BS_STAGE_U4 * 16);
        #pragma unroll
        for (int t = 0; t < 4; t++) {
            const int i = tid + t * 256;          // 1024 chunks
            const int kk = i >> 5, nq = i & 31;
            cp16(dstB + (uint32_t)(kk * 544 + nq * 16),
                 b + (size_t)kk * 128 + nq);
        }
        cp_commit();
    };

    load_tile(0, 0);
    load_tile(1, 1);

    int buf = 0;
    for (int kt = 0; kt < NKT; kt++) {
        if (kt + 1 < NKT) cp_wait1(); else cp_wait0();
        __syncthreads();          // tile kt visible; buffer (kt+2)%3 fully consumed

        // refill issued BEFORE compute: overlaps with this iteration's mma.
        if (kt + 2 < NKT) load_tile(kt + 2, (buf + 2 >= NSTAGE) ? buf + 2 - NSTAGE : buf + 2);

        const uint32_t* Ab = As32 + buf * (AS_STAGE_U4 * 4);
        const uint32_t* Bb = Bs32 + buf * (BS_STAGE_U4 * 4);
        #pragma unroll
        for (int k8 = 0; k8 < 4; k8++) {
            uint32_t a[2][4];
            const int kc = k8 * 8 + tig;
            #pragma unroll
            for (int mf = 0; mf < 2; mf++) {
                const int r0 = wm * 32 + mf * 16 + gid;
                a[mf][0] = Ab[r0 * 36 + kc];
                a[mf][1] = Ab[(r0 + 8) * 36 + kc];
                a[mf][2] = Ab[r0 * 36 + kc + 4];
                a[mf][3] = Ab[(r0 + 8) * 36 + kc + 4];
            }
            const uint32_t* Bp = Bb + (size_t)(k8 * 8 + tig) * 136 + wn * 64 + gid;
            #pragma unroll
            for (int nf = 0; nf < 8; nf++) {
                const uint32_t b0 = Bp[nf * 8];
                const uint32_t b1 = Bp[nf * 8 + 4 * 136];
                mma_tf32(acc[0][nf], a[0], b0, b1);
                mma_tf32(acc[1][nf], a[1], b0, b1);
            }
        }

        buf = (buf == NSTAGE - 1) ? 0 : buf + 1;
    }

    // -------- epilogue: score partials --------
    float part[4] = {0.f, 0.f, 0.f, 0.f};
    {
        // each warp's 32 rows lie inside one batch (wm*32 block within 64-row batch)
        const int b = (m0 + wm * 32) >> 6;
        const int off = b * 512 + n0 + wn * 64;
        const float* p0B = g_pp[0] + off;
        const float* p1B = g_pp[1] + off;
        const float* p2B = g_pp[2] + off;
        const float* p3B = g_pp[3] + off;
        const float* w3B = W3 + n0 + wn * 64;
        const float* wbB = Wb + n0 + wn * 64;
        #pragma unroll
        for (int nf = 0; nf < 8; nf++) {
            #pragma unroll
            for (int c = 0; c < 2; c++) {
                const int dl = nf * 8 + 2 * tig + c;
                const float add = wbB[dl] + p0B[dl] + p1B[dl] + p2B[dl] + p3B[dl];
                const float w3  = w3B[dl];
                float t0, t1, t2, t3;
                asm("tanh.approx.f32 %0, %1;" : "=f"(t0) : "f"(acc[0][nf][c]     + add));
                asm("tanh.approx.f32 %0, %1;" : "=f"(t1) : "f"(acc[0][nf][2 + c] + add));
                asm("tanh.approx.f32 %0, %1;" : "=f"(t2) : "f"(acc[1][nf][c]     + add));
                asm("tanh.approx.f32 %0, %1;" : "=f"(t3) : "f"(acc[1][nf][2 + c] + add));
                part[0] = fmaf(w3, t0, part[0]);   // row gid
                part[1] = fmaf(w3, t1, part[1]);   // row gid+8
                part[2] = fmaf(w3, t2, part[2]);   // row gid+16
                part[3] = fmaf(w3, t3, part[3]);   // row gid+24
            }
        }
    }
    // reduce over tig (lanes differing in bits 0..1 hold different d's)
    #pragma unroll
    for (int msk = 1; msk < 4; msk <<= 1) {
        #pragma unroll
        for (int i = 0; i < 4; i++)
            part[i] += __shfl_xor_sync(0xffffffffu, part[i], msk);
    }

    __syncthreads();                 // done with tile smem; repurpose
    float* scoreS = (float*)smem;    // [2][128]
    if (tig == 0) {
        const int rb = wm * 32 + gid;
        scoreS[wn * 128 + rb]      = part[0];
        scoreS[wn * 128 + rb + 8]  = part[1];
        scoreS[wn * 128 + rb + 16] = part[2];
        scoreS[wn * 128 + rb + 24] = part[3];
    }
    __syncthreads();
    if (tid < 128) {
        g_score[blockIdx.x * MROWS + m0 + tid] = scoreS[tid] + scoreS[128 + tid];
    }
}

// ---------------------------------------------------------------------------
// Kernel 3: softmax over 64 scores + weighted feature sum.
// grid (4 column-quarters, 256 batches), 128 threads; r-loop unroll 16.
// ---------------------------------------------------------------------------
__global__ void __launch_bounds__(128) softmax_q_kernel(
        const float* __restrict__ features,
        float* __restrict__ out) {
    __shared__ float s_s[64];
    __shared__ float aw_s[64];
    const int quarter = blockIdx.x;  // 0..3 (128 float4 columns each)
    const int b       = blockIdx.y;
    const int tid     = threadIdx.x;

    if (tid < 64) {
        float v = 0.f;
        #pragma unroll
        for (int p = 0; p < 4; p++) v += g_score[p * MROWS + b * 64 + tid];
        s_s[tid] = v;
    }
    __syncthreads();

    // every thread computes identical max/sum (deterministic, smem broadcast)
    float m = -1e30f;
    #pragma unroll 8
    for (int i = 0; i < 64; i++) m = fmaxf(m, s_s[i]);
    float sum = 0.f;
    #pragma unroll 8
    for (int i = 0; i < 64; i++) sum += expf(s_s[i] - m);

    if (tid < 64) aw_s[tid] = expf(s_s[tid] - m) / sum;
    __syncthreads();

    const int col = quarter * 128 + tid;       // float4 column index (0..511)
    const float4* f4 = (const float4*)(features + (size_t)b * R_ * F_) + col;
    float4 a0 = {0.f, 0.f, 0.f, 0.f};
    #pragma unroll
    for (int r = 0; r < 64; r += 16) {
        float4 x[16];
        float  w[16];
        #pragma unroll
        for (int j = 0; j < 16; j++) { x[j] = f4[(size_t)(r + j) * 512]; w[j] = aw_s[r + j]; }
        #pragma unroll
        for (int j = 0; j < 16; j++) {
            a0.x = fmaf(w[j], x[j].x, a0.x); a0.y = fmaf(w[j], x[j].y, a0.y);
            a0.z = fmaf(w[j], x[j].z, a0.z); a0.w = fmaf(w[j], x[j].w, a0.w);
        }
    }
    ((float4*)out)[(size_t)b * 512 + col] = a0;
}

// ---------------------------------------------------------------------------
// kernel_launch
// inputs: 0 features, 1 prev, 2 W_w, 3 W_b, 4 W2_w, 5 W2_b, 6 W3_w, 7 W3_b
// (W3_b unused: softmax is shift-invariant)
// order: cvt(3) steer(4) steer2(5) prep(6) gemm(7) softmax(8)
//  -> ncu slot 6 profiles prep_p (verifying the 4-way h-split)
// ---------------------------------------------------------------------------
extern "C" void kernel_launch(void* const* d_in, const int* in_sizes, int n_in,
                              void* d_out, int out_size) {
    const float* features = (const float*)d_in[0];
    const float* prev     = (const float*)d_in[1];
    const float* Ww       = (const float*)d_in[2];
    const float* Wb       = (const float*)d_in[3];
    const float* W2w      = (const float*)d_in[4];
    const float* W2b      = (const float*)d_in[5];
    const float* W3w      = (const float*)d_in[6];
    float* out = (float*)d_out;

    cudaFuncSetAttribute(gemm_score_kernel,
                         cudaFuncAttributeMaxDynamicSharedMemorySize, SMEM_BYTES);

    cvt_ww_kernel<<<(F_ * D_ / 4) / 256, 256>>>(Ww);
    steer_kernel<<<1, 1>>>();
    steer_kernel2<<<1, 1>>>();
    prep_p_kernel<<<dim3(64, 16), 128>>>(prev, W2w, W2b);
    gemm_score_kernel<<<dim3(4, 128), 256, SMEM_BYTES>>>(features, Wb, W3w);
    softmax_q_kernel<<<dim3(4, B_), 128>>>(features, out);
}

// round 16
// speedup vs baseline: 1.2391x; 1.0151x over previous
#include <cuda_runtime.h>
#include <cstdint>

// Problem shapes (fixed)
#define B_ 256
#define R_ 64
#define F_ 2048
#define H_ 512
#define D_ 512
#define MROWS (B_*R_)      // 16384 rows of the big GEMM

// GEMM tiling
#define KT 32              // K tile
#define MT 128             // M tile (2 batches)
#define NT 128             // N tile (4 n-chunks cover DIM=512)
#define NKT (F_/KT)        // 64 K iterations
#define NSTAGE 3

// smem: per stage A [128][9] uint4 (18432B), B [32][34] uint4 (17408B)
// B row stride 136 words: 136 mod 32 = 8 -> bank = 8*tig+gid (perfect perm)
#define AS_STAGE_U4 (128*9)                 // 1152
#define BS_STAGE_U4 (32*34)                 // 1088
#define AS_BYTES (NSTAGE*AS_STAGE_U4*16)    // 55296
#define BS_BYTES (NSTAGE*BS_STAGE_U4*16)    // 52224
#define SMEM_BYTES (AS_BYTES + BS_BYTES)    // 107520  (x2 CTAs = 215KB < 228KB)

// Scratch (device globals: no allocations allowed)
__device__ float    g_pp[8][B_ * D_];      // prev @ W2 partials per h-eighth
__device__ float    g_score[4 * MROWS];    // partial scores, one slab per n-chunk
__device__ uint32_t g_WwB[F_ * D_];        // W_w pre-rounded to tf32 (rna), same layout

// ---------------------------------------------------------------------------
// helpers
// ---------------------------------------------------------------------------
__device__ __forceinline__ void cp16(uint32_t dst, const void* src) {
    asm volatile("cp.async.cg.shared.global [%0], [%1], 16;" :: "r"(dst), "l"(src));
}
__device__ __forceinline__ uint32_t smem_u32(const void* p) {
    uint32_t a;
    asm("{ .reg .u64 t; cvta.to.shared.u64 t, %1; cvt.u32.u64 %0, t; }"
        : "=r"(a) : "l"(p));
    return a;
}
__device__ __forceinline__ void cp_commit() { asm volatile("cp.async.commit_group;"); }
__device__ __forceinline__ void cp_wait1()  { asm volatile("cp.async.wait_group 1;"); }
__device__ __forceinline__ void cp_wait0()  { asm volatile("cp.async.wait_group 0;"); }

__device__ __forceinline__ void mma_tf32(float* d, const uint32_t* a,
                                         uint32_t b0, uint32_t b1) {
    asm volatile(
        "mma.sync.aligned.m16n8k8.row.col.f32.tf32.tf32.f32 "
        "{%0,%1,%2,%3}, {%4,%5,%6,%7}, {%8,%9}, {%0,%1,%2,%3};\n"
        : "+f"(d[0]), "+f"(d[1]), "+f"(d[2]), "+f"(d[3])
        : "r"(a[0]), "r"(a[1]), "r"(a[2]), "r"(a[3]), "r"(b0), "r"(b1));
}

// ---------------------------------------------------------------------------
// Kernel 0: pre-round W_w to tf32 (rna) bits, same [F, D] layout
// ---------------------------------------------------------------------------
__global__ void __launch_bounds__(256) cvt_ww_kernel(const float* __restrict__ Ww) {
    const int i = blockIdx.x * 256 + threadIdx.x;      // uint4 index
    const float4 v = ((const float4*)Ww)[i];
    uint4 t;
    asm("cvt.rna.tf32.f32 %0, %1;" : "=r"(t.x) : "f"(v.x));
    asm("cvt.rna.tf32.f32 %0, %1;" : "=r"(t.y) : "f"(v.y));
    asm("cvt.rna.tf32.f32 %0, %1;" : "=r"(t.z) : "f"(v.z));
    asm("cvt.rna.tf32.f32 %0, %1;" : "=r"(t.w) : "f"(v.w));
    ((uint4*)g_WwB)[i] = t;
}

// ---------------------------------------------------------------------------
// Kernel 1: partial p over an h-eighth:
//   g_pp[hq][b,d] = sum_{h in eighth} prev[b,h]*W2w[h,d]  (+ W2b[d] if hq==0)
// grid (64 bg x 32), block 128: bg covers 4 batches; y = dq(4) + 4*hq(8).
// 2048 CTAs; per-thread chain 256 FMA; W2w loads 16-deep (MLP 16).
// ---------------------------------------------------------------------------
__global__ void __launch_bounds__(128) prep_p_kernel(
        const float* __restrict__ prev,
        const float* __restrict__ W2w,
        const float* __restrict__ W2b) {
    __shared__ float4 ps4[4 * 16];    // 4 batches x 64 floats (this h-eighth)
    const int bg  = blockIdx.x;       // 4 batches each
    const int dq  = blockIdx.y & 3;   // 128-d quarter
    const int hq  = blockIdx.y >> 2;  // h-eighth (0..7)
    const int tid = threadIdx.x;
    const int h0  = hq * 64;

    if (tid < 64) {
        const int bb = tid >> 4, hc = tid & 15;
        ps4[tid] = ((const float4*)(prev + (size_t)(bg * 4 + bb) * 512 + h0))[hc];
    }
    __syncthreads();

    const int d = dq * 128 + tid;
    float acc[4];
    const float init = (hq == 0) ? W2b[d] : 0.f;
    #pragma unroll
    for (int i = 0; i < 4; i++) acc[i] = init;

    #pragma unroll
    for (int h = 0; h < 64; h += 16) {
        float w[16];
        #pragma unroll
        for (int j = 0; j < 16; j++) w[j] = W2w[(h0 + h + j) * 512 + d];
        #pragma unroll
        for (int i = 0; i < 4; i++) {
            const float4 p0 = ps4[i * 16 + (h >> 2)];
            const float4 p1 = ps4[i * 16 + (h >> 2) + 1];
            const float4 p2 = ps4[i * 16 + (h >> 2) + 2];
            const float4 p3 = ps4[i * 16 + (h >> 2) + 3];
            acc[i] = fmaf(p0.x, w[0],  acc[i]);
            acc[i] = fmaf(p0.y, w[1],  acc[i]);
            acc[i] = fmaf(p0.z, w[2],  acc[i]);
            acc[i] = fmaf(p0.w, w[3],  acc[i]);
            acc[i] = fmaf(p1.x, w[4],  acc[i]);
            acc[i] = fmaf(p1.y, w[5],  acc[i]);
            acc[i] = fmaf(p1.z, w[6],  acc[i]);
            acc[i] = fmaf(p1.w, w[7],  acc[i]);
            acc[i] = fmaf(p2.x, w[8],  acc[i]);
            acc[i] = fmaf(p2.y, w[9],  acc[i]);
            acc[i] = fmaf(p2.z, w[10], acc[i]);
            acc[i] = fmaf(p2.w, w[11], acc[i]);
            acc[i] = fmaf(p3.x, w[12], acc[i]);
            acc[i] = fmaf(p3.y, w[13], acc[i]);
            acc[i] = fmaf(p3.z, w[14], acc[i]);
            acc[i] = fmaf(p3.w, w[15], acc[i]);
        }
    }
    float* gp = g_pp[hq];
    #pragma unroll
    for (int i = 0; i < 4; i++) gp[(size_t)(bg * 4 + i) * 512 + d] = acc[i];
}

// ---------------------------------------------------------------------------
// Kernel 2: per CTA, C[128,128] = feat_rows @ W_w[:, n-chunk] (tf32 mma.sync),
// then partial_score[row] = sum_d W3[d]*tanh(C + W_b[d] + sum_hq pp[hq][b,d])
// grid (4 n-chunks, 128 m-tiles), 256 threads, 2 CTAs/SM,
// single-barrier 3-stage cp.async pipeline (refill issued before mma)
// ---------------------------------------------------------------------------
__global__ void __launch_bounds__(256, 2) gemm_score_kernel(
        const float* __restrict__ features,
        const float* __restrict__ Wb,
        const float* __restrict__ W3) {
    extern __shared__ uint4 smem[];
    uint32_t* As32 = (uint32_t*)smem;                        // [3][128][36] words
    uint32_t* Bs32 = (uint32_t*)(smem + NSTAGE*AS_STAGE_U4); // [3][32][136] words
    const uint32_t sbase = smem_u32(smem);
    const uint32_t sA = sbase;
    const uint32_t sB = sbase + AS_BYTES;

    const int tid  = threadIdx.x;
    const int wid  = tid >> 5;
    const int lane = tid & 31;
    const int gid  = lane >> 2;       // group id (row within frag)
    const int tig  = lane & 3;        // thread-in-group (k/col within frag)
    const int wm   = wid & 3;         // warp m position (4 x 32 rows)
    const int wn   = wid >> 2;        // warp n position (2 x 64 cols)
    const int n0   = blockIdx.x * NT; // n-chunk (fast dim -> co-resident share A)
    const int m0   = blockIdx.y * MT;

    const float* gA = features + (size_t)m0 * F_;
    const uint4* Bw4 = (const uint4*)g_WwB;   // row stride 128 uint4

    float acc[2][8][4];
    #pragma unroll
    for (int i = 0; i < 2; i++)
        #pragma unroll
        for (int j = 0; j < 8; j++)
            #pragma unroll
            for (int k = 0; k < 4; k++) acc[i][j][k] = 0.f;

    // --- async tile load: A 128x32 floats, B 32x128 tf32-bits ---
    auto load_tile = [&](int kt, int buf) {
        const float* a = gA + kt * KT;
        const uint32_t dstA = sA + buf * (AS_STAGE_U4 * 16);
        #pragma unroll
        for (int t = 0; t < 4; t++) {
            const int i = tid + t * 256;          // 1024 chunks
            const int row = i >> 3, c = i & 7;
            cp16(dstA + (uint32_t)(row * 144 + c * 16),
                 a + (size_t)row * F_ + c * 4);
        }
        const uint4* b = Bw4 + (size_t)(kt * 32) * 128 + (n0 >> 2);
        const uint32_t dstB = sB + buf * (BS_STAGE_U4 * 16);
        #pragma unroll
        for (int t = 0; t < 4; t++) {
            const int i = tid + t * 256;          // 1024 chunks
            const int kk = i >> 5, nq = i & 31;
            cp16(dstB + (uint32_t)(kk * 544 + nq * 16),
                 b + (size_t)kk * 128 + nq);
        }
        cp_commit();
    };

    load_tile(0, 0);
    load_tile(1, 1);

    int buf = 0;
    for (int kt = 0; kt < NKT; kt++) {
        if (kt + 1 < NKT) cp_wait1(); else cp_wait0();
        __syncthreads();          // tile kt visible; buffer (kt+2)%3 fully consumed

        // refill issued BEFORE compute: overlaps with this iteration's mma.
        if (kt + 2 < NKT) load_tile(kt + 2, (buf + 2 >= NSTAGE) ? buf + 2 - NSTAGE : buf + 2);

        const uint32_t* Ab = As32 + buf * (AS_STAGE_U4 * 4);
        const uint32_t* Bb = Bs32 + buf * (BS_STAGE_U4 * 4);
        #pragma unroll
        for (int k8 = 0; k8 < 4; k8++) {
            uint32_t a[2][4];
            const int kc = k8 * 8 + tig;
            #pragma unroll
            for (int mf = 0; mf < 2; mf++) {
                const int r0 = wm * 32 + mf * 16 + gid;
                a[mf][0] = Ab[r0 * 36 + kc];
                a[mf][1] = Ab[(r0 + 8) * 36 + kc];
                a[mf][2] = Ab[r0 * 36 + kc + 4];
                a[mf][3] = Ab[(r0 + 8) * 36 + kc + 4];
            }
            const uint32_t* Bp = Bb + (size_t)(k8 * 8 + tig) * 136 + wn * 64 + gid;
            #pragma unroll
            for (int nf = 0; nf < 8; nf++) {
                const uint32_t b0 = Bp[nf * 8];
                const uint32_t b1 = Bp[nf * 8 + 4 * 136];
                mma_tf32(acc[0][nf], a[0], b0, b1);
                mma_tf32(acc[1][nf], a[1], b0, b1);
            }
        }

        buf = (buf == NSTAGE - 1) ? 0 : buf + 1;
    }

    // -------- epilogue: score partials --------
    float part[4] = {0.f, 0.f, 0.f, 0.f};
    {
        // each warp's 32 rows lie inside one batch (wm*32 block within 64-row batch)
        const int b = (m0 + wm * 32) >> 6;
        const int off = b * 512 + n0 + wn * 64;
        const float* w3B = W3 + n0 + wn * 64;
        const float* wbB = Wb + n0 + wn * 64;
        #pragma unroll
        for (int nf = 0; nf < 8; nf++) {
            #pragma unroll
            for (int c = 0; c < 2; c++) {
                const int dl = nf * 8 + 2 * tig + c;
                float add = wbB[dl];
                #pragma unroll
                for (int q = 0; q < 8; q++) add += g_pp[q][off + dl];
                const float w3  = w3B[dl];
                float t0, t1, t2, t3;
                asm("tanh.approx.f32 %0, %1;" : "=f"(t0) : "f"(acc[0][nf][c]     + add));
                asm("tanh.approx.f32 %0, %1;" : "=f"(t1) : "f"(acc[0][nf][2 + c] + add));
                asm("tanh.approx.f32 %0, %1;" : "=f"(t2) : "f"(acc[1][nf][c]     + add));
                asm("tanh.approx.f32 %0, %1;" : "=f"(t3) : "f"(acc[1][nf][2 + c] + add));
                part[0] = fmaf(w3, t0, part[0]);   // row gid
                part[1] = fmaf(w3, t1, part[1]);   // row gid+8
                part[2] = fmaf(w3, t2, part[2]);   // row gid+16
                part[3] = fmaf(w3, t3, part[3]);   // row gid+24
            }
        }
    }
    // reduce over tig (lanes differing in bits 0..1 hold different d's)
    #pragma unroll
    for (int msk = 1; msk < 4; msk <<= 1) {
        #pragma unroll
        for (int i = 0; i < 4; i++)
            part[i] += __shfl_xor_sync(0xffffffffu, part[i], msk);
    }

    __syncthreads();                 // done with tile smem; repurpose
    float* scoreS = (float*)smem;    // [2][128]
    if (tig == 0) {
        const int rb = wm * 32 + gid;
        scoreS[wn * 128 + rb]      = part[0];
        scoreS[wn * 128 + rb + 8]  = part[1];
        scoreS[wn * 128 + rb + 16] = part[2];
        scoreS[wn * 128 + rb + 24] = part[3];
    }
    __syncthreads();
    if (tid < 128) {
        g_score[blockIdx.x * MROWS + m0 + tid] = scoreS[tid] + scoreS[128 + tid];
    }
}

// ---------------------------------------------------------------------------
// Kernel 3: softmax over 64 scores + weighted feature sum.
// grid (4 column-quarters, 256 batches), 128 threads; r-loop unroll 16.
// ---------------------------------------------------------------------------
__global__ void __launch_bounds__(128) softmax_q_kernel(
        const float* __restrict__ features,
        float* __restrict__ out) {
    __shared__ float s_s[64];
    __shared__ float aw_s[64];
    const int quarter = blockIdx.x;  // 0..3 (128 float4 columns each)
    const int b       = blockIdx.y;
    const int tid     = threadIdx.x;

    if (tid < 64) {
        float v = 0.f;
        #pragma unroll
        for (int p = 0; p < 4; p++) v += g_score[p * MROWS + b * 64 + tid];
        s_s[tid] = v;
    }
    __syncthreads();

    // every thread computes identical max/sum (deterministic, smem broadcast)
    float m = -1e30f;
    #pragma unroll 8
    for (int i = 0; i < 64; i++) m = fmaxf(m, s_s[i]);
    float sum = 0.f;
    #pragma unroll 8
    for (int i = 0; i < 64; i++) sum += expf(s_s[i] - m);

    if (tid < 64) aw_s[tid] = expf(s_s[tid] - m) / sum;
    __syncthreads();

    const int col = quarter * 128 + tid;       // float4 column index (0..511)
    const float4* f4 = (const float4*)(features + (size_t)b * R_ * F_) + col;
    float4 a0 = {0.f, 0.f, 0.f, 0.f};
    #pragma unroll
    for (int r = 0; r < 64; r += 16) {
        float4 x[16];
        float  w[16];
        #pragma unroll
        for (int j = 0; j < 16; j++) { x[j] = f4[(size_t)(r + j) * 512]; w[j] = aw_s[r + j]; }
        #pragma unroll
        for (int j = 0; j < 16; j++) {
            a0.x = fmaf(w[j], x[j].x, a0.x); a0.y = fmaf(w[j], x[j].y, a0.y);
            a0.z = fmaf(w[j], x[j].z, a0.z); a0.w = fmaf(w[j], x[j].w, a0.w);
        }
    }
    ((float4*)out)[(size_t)b * 512 + col] = a0;
}

// ---------------------------------------------------------------------------
// kernel_launch
// inputs: 0 features, 1 prev, 2 W_w, 3 W_b, 4 W2_w, 5 W2_b, 6 W3_w, 7 W3_b
// (W3_b unused: softmax is shift-invariant)
// order: cvt(3) prep(4) gemm(5) softmax(6) -> ncu slot 6 profiles softmax
// ---------------------------------------------------------------------------
extern "C" void kernel_launch(void* const* d_in, const int* in_sizes, int n_in,
                              void* d_out, int out_size) {
    const float* features = (const float*)d_in[0];
    const float* prev     = (const float*)d_in[1];
    const float* Ww       = (const float*)d_in[2];
    const float* Wb       = (const float*)d_in[3];
    const float* W2w      = (const float*)d_in[4];
    const float* W2b      = (const float*)d_in[5];
    const float* W3w      = (const float*)d_in[6];
    float* out = (float*)d_out;

    cudaFuncSetAttribute(gemm_score_kernel,
                         cudaFuncAttributeMaxDynamicSharedMemorySize, SMEM_BYTES);

    cvt_ww_kernel<<<(F_ * D_ / 4) / 256, 256>>>(Ww);
    prep_p_kernel<<<dim3(64, 32), 128>>>(prev, W2w, W2b);
    gemm_score_kernel<<<dim3(4, 128), 256, SMEM_BYTES>>>(features, Wb, W3w);
    softmax_q_kernel<<<dim3(4, B_), 128>>>(features, out);
}